// round 5
// baseline (speedup 1.0000x reference)
#include <cuda_runtime.h>

// CapsNet dynamic routing, persistent kernel, round 5.
// 144 CTAs x 1024 threads, KL=8 k's per CTA. u_hat: 384 b in smem (swizzled),
// 128 b in registers, fp32, f32x2 packed FMA. x via direct LDG.128, fused
// phase1(it=0) in the build.
// Round-5: grid barrier with per-CTA sense lines (no poll contention) +
// nanosleep backoff (tight spin was the R3/R4 regression); skip the dead
// final phase-3 and final barrier.

#define NCTA 144
#define THREADS 1024
#define KL 8
#define BATCH 512
#define JOUT 10
#define ITERS 3
#define SB 384          // b's with u_hat in smem
#define SQ 6            // smem chunks of 64 b
#define RQ 2            // register chunks of 64 b
#define NCH 8           // total chunks
#define UHB 128         // floats per b row (swizzled, no pad)
#define WTB 68          // w_t row stride

#define SMEM_FLOATS (SB*UHB + 16*WTB + KL*JOUT + KL + 1024)
#define SMEM_BYTES (SMEM_FLOATS * 4)

typedef unsigned long long ull;

__device__ float g_spart[NCTA * BATCH * 16];
__device__ float g_v[BATCH * 16];
__device__ unsigned g_count;
__device__ unsigned g_senses[NCTA * 32];   // one 128B line per CTA

__device__ __forceinline__ ull f2_pk(float lo, float hi) {
    ull r; asm("mov.b64 %0,{%1,%2};" : "=l"(r) : "f"(lo), "f"(hi)); return r;
}
__device__ __forceinline__ float2 f2_up(ull a) {
    float2 r; asm("mov.b64 {%0,%1},%2;" : "=f"(r.x), "=f"(r.y) : "l"(a)); return r;
}
__device__ __forceinline__ ull f2_fma(ull a, ull b, ull c) {
    ull d; asm("fma.rn.f32x2 %0,%1,%2,%3;" : "=l"(d) : "l"(a), "l"(b), "l"(c)); return d;
}
__device__ __forceinline__ ull f2_mul(ull a, ull b) {
    ull d; asm("mul.rn.f32x2 %0,%1,%2;" : "=l"(d) : "l"(a), "l"(b)); return d;
}
__device__ __forceinline__ ull f2_add(ull a, ull b) {
    ull d; asm("add.rn.f32x2 %0,%1,%2;" : "=l"(d) : "l"(a), "l"(b)); return d;
}

// swizzled word offset of the h-th float4 (h=0: kl0-3, h=1: kl4-7) for vector idx u
__device__ __forceinline__ int uoff(int u, int h) { return (u * 8 + h * 4) ^ (u & 4); }

// Grid barrier: atomic arrival count + per-CTA sense lines. Each waiter polls
// ONLY its own 128B line (no L2 hot-line contention); the last arriver resets
// the count and broadcasts gen+1 to all lines. Monotonic gen, zero-reset count:
// graph-replay safe with no end-of-kernel cleanup.
__device__ __forceinline__ void grid_barrier(int cta) {
    __syncthreads();
    if (threadIdx.x == 0) {
        volatile unsigned* mine = &g_senses[cta * 32];
        const unsigned gen = *mine;            // stable between barriers
        __threadfence();                       // release prior global writes
        if (atomicAdd(&g_count, 1u) == NCTA - 1) {
            g_count = 0;                       // all arrived; waiters gated by sense
            __threadfence();
            #pragma unroll 4
            for (int i = 0; i < NCTA; ++i)
                *(volatile unsigned*)&g_senses[i * 32] = gen + 1u;
        } else {
            while (*mine == gen) __nanosleep(64);
        }
        __threadfence();                       // acquire
    }
    __syncthreads();
}

__global__ void __launch_bounds__(THREADS, 1)
caps_routing_kernel(const float* __restrict__ x,   // [512,1152,8]
                    const float* __restrict__ W,   // [10,1152,8,16]
                    float* __restrict__ out)       // [512,10,16]
{
    extern __shared__ float sm[];
    float* uh_s    = sm;                     // SB*UHB
    float* w_t     = uh_s + SB * UHB;        // 16*WTB : w_t[u][kl*8+d]
    float* bs      = w_t + 16 * WTB;         // KL*JOUT b_IJ rows
    float* c_s     = bs + KL * JOUT;         // KL coupling coeffs
    float* scratch = c_s + KL;               // 1024 reduction scratch

    const int t    = threadIdx.x;
    const int cta  = blockIdx.x;
    const int k0   = cta * KL;
    const int u    = t & 15;
    const int bg   = t >> 4;                 // 0..63
    const int lane = t & 31;
    const int warp = t >> 5;

    ull uhr[RQ][4];                          // register u_hat for b in [384,512)

    for (int i = t; i < KL * JOUT; i += THREADS) bs[i] = 0.f;
    if (t < KL) c_s[t] = 0.1f;               // softmax(0) over 10
    __syncthreads();

    // base of this thread's x rows: x[b=bg+64*ch, k0.., :], advanced by qi*16
    const float* xbase = x + ((size_t)bg * 1152 + k0) * 8;

    for (int j = 0; j < JOUT; ++j) {
        // ---- W[j, k0+kl, d, uu] -> w_t[uu][kl*8+d] ----
        {
            const int kl = t >> 7, rest = t & 127;
            const int d = rest >> 4, uu = rest & 15;
            w_t[uu * WTB + kl * 8 + d] = W[(size_t)(j * 1152 + k0 + kl) * 128 + rest];
        }
        __syncthreads();

        float s0acc[NCH];                     // fused phase1 (it=0) accumulators
        #pragma unroll
        for (int ch = 0; ch < NCH; ++ch) s0acc[ch] = 0.f;

        // ---- build u_hat + fused s0; x read directly from global ----
        #pragma unroll
        for (int qi = 0; qi < 4; ++qi) {
            const ulonglong2 Wq0a = *reinterpret_cast<const ulonglong2*>(w_t + u * WTB + (qi * 2 + 0) * 8);
            const ulonglong2 Wq0b = *reinterpret_cast<const ulonglong2*>(w_t + u * WTB + (qi * 2 + 0) * 8 + 4);
            const ulonglong2 Wq1a = *reinterpret_cast<const ulonglong2*>(w_t + u * WTB + (qi * 2 + 1) * 8);
            const ulonglong2 Wq1b = *reinterpret_cast<const ulonglong2*>(w_t + u * WTB + (qi * 2 + 1) * 8 + 4);
            const float clo = c_s[qi * 2], chi = c_s[qi * 2 + 1];
            const float* xq = xbase + qi * 16;

            #pragma unroll
            for (int ch = 0; ch < NCH; ++ch) {
                const float* xr = xq + (size_t)ch * 64 * 9216;  // b = ch*64+bg
                const ulonglong2 X0 = *reinterpret_cast<const ulonglong2*>(xr);
                const ulonglong2 X1 = *reinterpret_cast<const ulonglong2*>(xr + 4);
                const ulonglong2 X2 = *reinterpret_cast<const ulonglong2*>(xr + 8);
                const ulonglong2 X3 = *reinterpret_cast<const ulonglong2*>(xr + 12);

                float a0, a1;
                {
                    ull acc = f2_mul(X0.x, Wq0a.x);
                    acc = f2_fma(X0.y, Wq0a.y, acc);
                    acc = f2_fma(X1.x, Wq0b.x, acc);
                    acc = f2_fma(X1.y, Wq0b.y, acc);
                    const float2 p = f2_up(acc);
                    a0 = p.x + p.y;
                }
                {
                    ull acc = f2_mul(X2.x, Wq1a.x);
                    acc = f2_fma(X2.y, Wq1a.y, acc);
                    acc = f2_fma(X3.x, Wq1b.x, acc);
                    acc = f2_fma(X3.y, Wq1b.y, acc);
                    const float2 p = f2_up(acc);
                    a1 = p.x + p.y;
                }
                s0acc[ch] = fmaf(a1, chi, fmaf(a0, clo, s0acc[ch]));
                if (ch < SQ) {
                    const int off = (u * 8 + qi * 2) ^ (u & 4);
                    *reinterpret_cast<float2*>(uh_s + (ch * 64 + bg) * UHB + off)
                        = make_float2(a0, a1);
                } else {
                    uhr[ch - SQ][qi] = f2_pk(a0, a1);
                }
            }
        }

        // fused phase1 (it=0) store
        #pragma unroll
        for (int ch = 0; ch < NCH; ++ch)
            __stcg(&g_spart[((size_t)cta * BATCH + ch * 64 + bg) * 16 + u], s0acc[ch]);

        for (int it = 0; it < ITERS; ++it) {
            const bool last = (j == JOUT - 1) && (it == ITERS - 1);

            // ---------- phase 1 (it>=1): partial s over this CTA's 8 k's ----------
            if (it > 0) {
                const ull c01 = f2_pk(c_s[0], c_s[1]);
                const ull c23 = f2_pk(c_s[2], c_s[3]);
                const ull c45 = f2_pk(c_s[4], c_s[5]);
                const ull c67 = f2_pk(c_s[6], c_s[7]);
                #pragma unroll
                for (int q = 0; q < SQ; ++q) {
                    const int b = q * 64 + bg;
                    const float* src = uh_s + b * UHB;
                    const ulonglong2 A  = *reinterpret_cast<const ulonglong2*>(src + uoff(u, 0));
                    const ulonglong2 Bv = *reinterpret_cast<const ulonglong2*>(src + uoff(u, 1));
                    ull s0 = f2_mul(A.x, c01);
                    ull s1 = f2_mul(A.y, c23);
                    s0 = f2_fma(Bv.x, c45, s0);
                    s1 = f2_fma(Bv.y, c67, s1);
                    const float2 p = f2_up(f2_add(s0, s1));
                    __stcg(&g_spart[((size_t)cta * BATCH + b) * 16 + u], p.x + p.y);
                }
                #pragma unroll
                for (int q = 0; q < RQ; ++q) {
                    const int b = SB + q * 64 + bg;
                    ull s0 = f2_mul(uhr[q][0], c01);
                    ull s1 = f2_mul(uhr[q][1], c23);
                    s0 = f2_fma(uhr[q][2], c45, s0);
                    s1 = f2_fma(uhr[q][3], c67, s1);
                    const float2 p = f2_up(f2_add(s0, s1));
                    __stcg(&g_spart[((size_t)cta * BATCH + b) * 16 + u], p.x + p.y);
                }
            }
            grid_barrier(cta);

            // ---------- phase 2: reduce 144 partials, squash -> v ----------
            if (cta < 128) {
                const int bl  = (t >> 4) & 3;
                const int ch2 = t >> 6;                     // 0..15
                const int b   = cta * 4 + bl;
                float p = 0.f;
                for (int i = ch2; i < NCTA; i += 16)
                    p += __ldcg(&g_spart[((size_t)i * BATCH + b) * 16 + u]);
                scratch[ch2 * 64 + bl * 16 + u] = p;
                __syncthreads();
                if (t < 64) {
                    float s = 0.f;
                    #pragma unroll
                    for (int c2 = 0; c2 < 16; ++c2) s += scratch[c2 * 64 + t];
                    float sq = s * s;
                    #pragma unroll
                    for (int m = 8; m >= 1; m >>= 1)
                        sq += __shfl_xor_sync(0xffffffffu, sq, m);
                    const float v = s * sq / ((1.f + sq) * (sqrtf(sq) + 1e-7f));
                    const int bb = cta * 4 + (t >> 4);
                    if (!last)
                        __stcg(&g_v[bb * 16 + (t & 15)], v);
                    if (it == ITERS - 1)
                        out[((size_t)bb * JOUT + j) * 16 + (t & 15)] = v;
                }
            }
            if (last) break;                   // final v written to out; no p3 needed
            grid_barrier(cta);

            // ---------- phase 3: agree, b_IJ update, next c (CTA-local) ----------
            {
                ull ag0 = 0ull, ag1 = 0ull, ag2 = 0ull, ag3 = 0ull;
                #pragma unroll
                for (int q = 0; q < SQ; ++q) {
                    const int b = q * 64 + bg;
                    const float vv = __ldcg(&g_v[b * 16 + u]);
                    const ull vp = f2_pk(vv, vv);
                    const float* src = uh_s + b * UHB;
                    const ulonglong2 A  = *reinterpret_cast<const ulonglong2*>(src + uoff(u, 0));
                    const ulonglong2 Bv = *reinterpret_cast<const ulonglong2*>(src + uoff(u, 1));
                    ag0 = f2_fma(A.x,  vp, ag0);
                    ag1 = f2_fma(A.y,  vp, ag1);
                    ag2 = f2_fma(Bv.x, vp, ag2);
                    ag3 = f2_fma(Bv.y, vp, ag3);
                }
                #pragma unroll
                for (int q = 0; q < RQ; ++q) {
                    const int b = SB + q * 64 + bg;
                    const float vv = __ldcg(&g_v[b * 16 + u]);
                    const ull vp = f2_pk(vv, vv);
                    ag0 = f2_fma(uhr[q][0], vp, ag0);
                    ag1 = f2_fma(uhr[q][1], vp, ag1);
                    ag2 = f2_fma(uhr[q][2], vp, ag2);
                    ag3 = f2_fma(uhr[q][3], vp, ag3);
                }
                float ag[8];
                { float2 p;
                  p = f2_up(ag0); ag[0] = p.x; ag[1] = p.y;
                  p = f2_up(ag1); ag[2] = p.x; ag[3] = p.y;
                  p = f2_up(ag2); ag[4] = p.x; ag[5] = p.y;
                  p = f2_up(ag3); ag[6] = p.x; ag[7] = p.y; }
                #pragma unroll
                for (int kl = 0; kl < KL; ++kl) {
                    float v = ag[kl];
                    #pragma unroll
                    for (int m = 16; m >= 1; m >>= 1)
                        v += __shfl_xor_sync(0xffffffffu, v, m);
                    if (lane == 0) scratch[warp * KL + kl] = v;
                }
                __syncthreads();
                if (t < KL) {
                    float s = 0.f;
                    #pragma unroll
                    for (int w2 = 0; w2 < 32; ++w2) s += scratch[w2 * KL + t];
                    bs[t * JOUT + j] += s;
                    const int jn = (it < ITERS - 1) ? j : j + 1;
                    if (jn < JOUT) {
                        float m = bs[t * JOUT];
                        #pragma unroll
                        for (int jj = 1; jj < JOUT; ++jj)
                            m = fmaxf(m, bs[t * JOUT + jj]);
                        float den = 0.f, num = 0.f;
                        #pragma unroll
                        for (int jj = 0; jj < JOUT; ++jj) {
                            const float e = expf(bs[t * JOUT + jj] - m);
                            den += e;
                            if (jj == jn) num = e;
                        }
                        c_s[t] = num / den;
                    }
                }
                __syncthreads();
            }
        } // it
    } // j
}

extern "C" void kernel_launch(void* const* d_in, const int* in_sizes, int n_in,
                              void* d_out, int out_size) {
    const float* x = (const float*)d_in[0];   // [512,1152,8,1]
    const float* W = (const float*)d_in[1];   // [10,1152,8,16]
    float* out = (float*)d_out;               // [512,10,16,1]
    (void)in_sizes; (void)n_in; (void)out_size;

    cudaFuncSetAttribute(caps_routing_kernel,
                         cudaFuncAttributeMaxDynamicSharedMemorySize, SMEM_BYTES);
    caps_routing_kernel<<<NCTA, THREADS, SMEM_BYTES>>>(x, W, out);
}

// round 6
// speedup vs baseline: 1.1466x; 1.1466x over previous
#include <cuda_runtime.h>

// CapsNet dynamic routing, persistent kernel, round 6.
// = R4 compute path (direct LDG.128 x, fused phase1(it=0) in the build,
//   dead final phase-3 skipped)  +  R2 barrier (single sense line,
//   nanosleep(64) backoff) which benchmarked best across R2-R5.

#define NCTA 144
#define THREADS 1024
#define KL 8
#define BATCH 512
#define JOUT 10
#define ITERS 3
#define SB 384          // b's with u_hat in smem
#define SQ 6            // smem chunks of 64 b
#define RQ 2            // register chunks of 64 b
#define NCH 8           // total chunks
#define UHB 128         // floats per b row (swizzled, no pad)
#define WTB 68          // w_t row stride

#define SMEM_FLOATS (SB*UHB + 16*WTB + KL*JOUT + KL + 1024)
#define SMEM_BYTES (SMEM_FLOATS * 4)

typedef unsigned long long ull;

__device__ float g_spart[NCTA * BATCH * 16];
__device__ float g_v[BATCH * 16];
__device__ unsigned g_count;
__device__ volatile unsigned g_sense;

__device__ __forceinline__ ull f2_pk(float lo, float hi) {
    ull r; asm("mov.b64 %0,{%1,%2};" : "=l"(r) : "f"(lo), "f"(hi)); return r;
}
__device__ __forceinline__ float2 f2_up(ull a) {
    float2 r; asm("mov.b64 {%0,%1},%2;" : "=f"(r.x), "=f"(r.y) : "l"(a)); return r;
}
__device__ __forceinline__ ull f2_fma(ull a, ull b, ull c) {
    ull d; asm("fma.rn.f32x2 %0,%1,%2,%3;" : "=l"(d) : "l"(a), "l"(b), "l"(c)); return d;
}
__device__ __forceinline__ ull f2_mul(ull a, ull b) {
    ull d; asm("mul.rn.f32x2 %0,%1,%2;" : "=l"(d) : "l"(a), "l"(b)); return d;
}
__device__ __forceinline__ ull f2_add(ull a, ull b) {
    ull d; asm("add.rn.f32x2 %0,%1,%2;" : "=l"(d) : "l"(a), "l"(b)); return d;
}

// swizzled word offset of the h-th float4 (h=0: kl0-3, h=1: kl4-7) for vector idx u
__device__ __forceinline__ int uoff(int u, int h) { return (u * 8 + h * 4) ^ (u & 4); }

// R2 barrier: atomicAdd arrivals on one counter, last arriver resets count and
// bumps the single sense word; waiters poll it with nanosleep backoff.
// Monotonic sense + count returning to 0 each barrier -> graph-replay safe.
__device__ __forceinline__ void grid_barrier() {
    __syncthreads();
    if (threadIdx.x == 0) {
        __threadfence();                       // release
        const unsigned gen = g_sense;
        if (atomicAdd(&g_count, 1u) == NCTA - 1) {
            g_count = 0;                       // all arrived; waiters gated by sense
            __threadfence();
            g_sense = gen + 1;
        } else {
            while (g_sense == gen) __nanosleep(64);
        }
        __threadfence();                       // acquire
    }
    __syncthreads();
}

__global__ void __launch_bounds__(THREADS, 1)
caps_routing_kernel(const float* __restrict__ x,   // [512,1152,8]
                    const float* __restrict__ W,   // [10,1152,8,16]
                    float* __restrict__ out)       // [512,10,16]
{
    extern __shared__ float sm[];
    float* uh_s    = sm;                     // SB*UHB
    float* w_t     = uh_s + SB * UHB;        // 16*WTB : w_t[u][kl*8+d]
    float* bs      = w_t + 16 * WTB;         // KL*JOUT b_IJ rows
    float* c_s     = bs + KL * JOUT;         // KL coupling coeffs
    float* scratch = c_s + KL;               // 1024 reduction scratch

    const int t    = threadIdx.x;
    const int cta  = blockIdx.x;
    const int k0   = cta * KL;
    const int u    = t & 15;
    const int bg   = t >> 4;                 // 0..63
    const int lane = t & 31;
    const int warp = t >> 5;

    ull uhr[RQ][4];                          // register u_hat for b in [384,512)

    for (int i = t; i < KL * JOUT; i += THREADS) bs[i] = 0.f;
    if (t < KL) c_s[t] = 0.1f;               // softmax(0) over 10
    __syncthreads();

    // base of this thread's x rows: x[b=bg+64*ch, k0.., :], advanced by qi*16
    const float* xbase = x + ((size_t)bg * 1152 + k0) * 8;

    for (int j = 0; j < JOUT; ++j) {
        // ---- W[j, k0+kl, d, uu] -> w_t[uu][kl*8+d] ----
        {
            const int kl = t >> 7, rest = t & 127;
            const int d = rest >> 4, uu = rest & 15;
            w_t[uu * WTB + kl * 8 + d] = W[(size_t)(j * 1152 + k0 + kl) * 128 + rest];
        }
        __syncthreads();

        float s0acc[NCH];                     // fused phase1 (it=0) accumulators
        #pragma unroll
        for (int ch = 0; ch < NCH; ++ch) s0acc[ch] = 0.f;

        // ---- build u_hat + fused s0; x read directly from global ----
        #pragma unroll
        for (int qi = 0; qi < 4; ++qi) {
            const ulonglong2 Wq0a = *reinterpret_cast<const ulonglong2*>(w_t + u * WTB + (qi * 2 + 0) * 8);
            const ulonglong2 Wq0b = *reinterpret_cast<const ulonglong2*>(w_t + u * WTB + (qi * 2 + 0) * 8 + 4);
            const ulonglong2 Wq1a = *reinterpret_cast<const ulonglong2*>(w_t + u * WTB + (qi * 2 + 1) * 8);
            const ulonglong2 Wq1b = *reinterpret_cast<const ulonglong2*>(w_t + u * WTB + (qi * 2 + 1) * 8 + 4);
            const float clo = c_s[qi * 2], chi = c_s[qi * 2 + 1];
            const float* xq = xbase + qi * 16;

            #pragma unroll
            for (int ch = 0; ch < NCH; ++ch) {
                const float* xr = xq + (size_t)ch * 64 * 9216;  // b = ch*64+bg
                const ulonglong2 X0 = *reinterpret_cast<const ulonglong2*>(xr);
                const ulonglong2 X1 = *reinterpret_cast<const ulonglong2*>(xr + 4);
                const ulonglong2 X2 = *reinterpret_cast<const ulonglong2*>(xr + 8);
                const ulonglong2 X3 = *reinterpret_cast<const ulonglong2*>(xr + 12);

                float a0, a1;
                {
                    ull acc = f2_mul(X0.x, Wq0a.x);
                    acc = f2_fma(X0.y, Wq0a.y, acc);
                    acc = f2_fma(X1.x, Wq0b.x, acc);
                    acc = f2_fma(X1.y, Wq0b.y, acc);
                    const float2 p = f2_up(acc);
                    a0 = p.x + p.y;
                }
                {
                    ull acc = f2_mul(X2.x, Wq1a.x);
                    acc = f2_fma(X2.y, Wq1a.y, acc);
                    acc = f2_fma(X3.x, Wq1b.x, acc);
                    acc = f2_fma(X3.y, Wq1b.y, acc);
                    const float2 p = f2_up(acc);
                    a1 = p.x + p.y;
                }
                s0acc[ch] = fmaf(a1, chi, fmaf(a0, clo, s0acc[ch]));
                if (ch < SQ) {
                    const int off = (u * 8 + qi * 2) ^ (u & 4);
                    *reinterpret_cast<float2*>(uh_s + (ch * 64 + bg) * UHB + off)
                        = make_float2(a0, a1);
                } else {
                    uhr[ch - SQ][qi] = f2_pk(a0, a1);
                }
            }
        }

        // fused phase1 (it=0) store
        #pragma unroll
        for (int ch = 0; ch < NCH; ++ch)
            __stcg(&g_spart[((size_t)cta * BATCH + ch * 64 + bg) * 16 + u], s0acc[ch]);

        for (int it = 0; it < ITERS; ++it) {
            const bool last = (j == JOUT - 1) && (it == ITERS - 1);

            // ---------- phase 1 (it>=1): partial s over this CTA's 8 k's ----------
            if (it > 0) {
                const ull c01 = f2_pk(c_s[0], c_s[1]);
                const ull c23 = f2_pk(c_s[2], c_s[3]);
                const ull c45 = f2_pk(c_s[4], c_s[5]);
                const ull c67 = f2_pk(c_s[6], c_s[7]);
                #pragma unroll
                for (int q = 0; q < SQ; ++q) {
                    const int b = q * 64 + bg;
                    const float* src = uh_s + b * UHB;
                    const ulonglong2 A  = *reinterpret_cast<const ulonglong2*>(src + uoff(u, 0));
                    const ulonglong2 Bv = *reinterpret_cast<const ulonglong2*>(src + uoff(u, 1));
                    ull s0 = f2_mul(A.x, c01);
                    ull s1 = f2_mul(A.y, c23);
                    s0 = f2_fma(Bv.x, c45, s0);
                    s1 = f2_fma(Bv.y, c67, s1);
                    const float2 p = f2_up(f2_add(s0, s1));
                    __stcg(&g_spart[((size_t)cta * BATCH + b) * 16 + u], p.x + p.y);
                }
                #pragma unroll
                for (int q = 0; q < RQ; ++q) {
                    const int b = SB + q * 64 + bg;
                    ull s0 = f2_mul(uhr[q][0], c01);
                    ull s1 = f2_mul(uhr[q][1], c23);
                    s0 = f2_fma(uhr[q][2], c45, s0);
                    s1 = f2_fma(uhr[q][3], c67, s1);
                    const float2 p = f2_up(f2_add(s0, s1));
                    __stcg(&g_spart[((size_t)cta * BATCH + b) * 16 + u], p.x + p.y);
                }
            }
            grid_barrier();

            // ---------- phase 2: reduce 144 partials, squash -> v ----------
            if (cta < 128) {
                const int bl  = (t >> 4) & 3;
                const int ch2 = t >> 6;                     // 0..15
                const int b   = cta * 4 + bl;
                float p = 0.f;
                for (int i = ch2; i < NCTA; i += 16)
                    p += __ldcg(&g_spart[((size_t)i * BATCH + b) * 16 + u]);
                scratch[ch2 * 64 + bl * 16 + u] = p;
                __syncthreads();
                if (t < 64) {
                    float s = 0.f;
                    #pragma unroll
                    for (int c2 = 0; c2 < 16; ++c2) s += scratch[c2 * 64 + t];
                    float sq = s * s;
                    #pragma unroll
                    for (int m = 8; m >= 1; m >>= 1)
                        sq += __shfl_xor_sync(0xffffffffu, sq, m);
                    const float v = s * sq / ((1.f + sq) * (sqrtf(sq) + 1e-7f));
                    const int bb = cta * 4 + (t >> 4);
                    if (!last)
                        __stcg(&g_v[bb * 16 + (t & 15)], v);
                    if (it == ITERS - 1)
                        out[((size_t)bb * JOUT + j) * 16 + (t & 15)] = v;
                }
            }
            if (last) break;                   // final v written to out; no p3 needed
            grid_barrier();

            // ---------- phase 3: agree, b_IJ update, next c (CTA-local) ----------
            {
                ull ag0 = 0ull, ag1 = 0ull, ag2 = 0ull, ag3 = 0ull;
                #pragma unroll
                for (int q = 0; q < SQ; ++q) {
                    const int b = q * 64 + bg;
                    const float vv = __ldcg(&g_v[b * 16 + u]);
                    const ull vp = f2_pk(vv, vv);
                    const float* src = uh_s + b * UHB;
                    const ulonglong2 A  = *reinterpret_cast<const ulonglong2*>(src + uoff(u, 0));
                    const ulonglong2 Bv = *reinterpret_cast<const ulonglong2*>(src + uoff(u, 1));
                    ag0 = f2_fma(A.x,  vp, ag0);
                    ag1 = f2_fma(A.y,  vp, ag1);
                    ag2 = f2_fma(Bv.x, vp, ag2);
                    ag3 = f2_fma(Bv.y, vp, ag3);
                }
                #pragma unroll
                for (int q = 0; q < RQ; ++q) {
                    const int b = SB + q * 64 + bg;
                    const float vv = __ldcg(&g_v[b * 16 + u]);
                    const ull vp = f2_pk(vv, vv);
                    ag0 = f2_fma(uhr[q][0], vp, ag0);
                    ag1 = f2_fma(uhr[q][1], vp, ag1);
                    ag2 = f2_fma(uhr[q][2], vp, ag2);
                    ag3 = f2_fma(uhr[q][3], vp, ag3);
                }
                float ag[8];
                { float2 p;
                  p = f2_up(ag0); ag[0] = p.x; ag[1] = p.y;
                  p = f2_up(ag1); ag[2] = p.x; ag[3] = p.y;
                  p = f2_up(ag2); ag[4] = p.x; ag[5] = p.y;
                  p = f2_up(ag3); ag[6] = p.x; ag[7] = p.y; }
                #pragma unroll
                for (int kl = 0; kl < KL; ++kl) {
                    float v = ag[kl];
                    #pragma unroll
                    for (int m = 16; m >= 1; m >>= 1)
                        v += __shfl_xor_sync(0xffffffffu, v, m);
                    if (lane == 0) scratch[warp * KL + kl] = v;
                }
                __syncthreads();
                if (t < KL) {
                    float s = 0.f;
                    #pragma unroll
                    for (int w2 = 0; w2 < 32; ++w2) s += scratch[w2 * KL + t];
                    bs[t * JOUT + j] += s;
                    const int jn = (it < ITERS - 1) ? j : j + 1;
                    if (jn < JOUT) {
                        float m = bs[t * JOUT];
                        #pragma unroll
                        for (int jj = 1; jj < JOUT; ++jj)
                            m = fmaxf(m, bs[t * JOUT + jj]);
                        float den = 0.f, num = 0.f;
                        #pragma unroll
                        for (int jj = 0; jj < JOUT; ++jj) {
                            const float e = expf(bs[t * JOUT + jj] - m);
                            den += e;
                            if (jj == jn) num = e;
                        }
                        c_s[t] = num / den;
                    }
                }
                __syncthreads();
            }
        } // it
    } // j
}

extern "C" void kernel_launch(void* const* d_in, const int* in_sizes, int n_in,
                              void* d_out, int out_size) {
    const float* x = (const float*)d_in[0];   // [512,1152,8,1]
    const float* W = (const float*)d_in[1];   // [10,1152,8,16]
    float* out = (float*)d_out;               // [512,10,16,1]
    (void)in_sizes; (void)n_in; (void)out_size;

    cudaFuncSetAttribute(caps_routing_kernel,
                         cudaFuncAttributeMaxDynamicSharedMemorySize, SMEM_BYTES);
    caps_routing_kernel<<<NCTA, THREADS, SMEM_BYTES>>>(x, W, out);
}

// round 7
// speedup vs baseline: 1.2386x; 1.0802x over previous
#include <cuda_runtime.h>

// CapsNet dynamic routing, persistent kernel, round 7.
// = R2 base (smem-staged x build, single-sense nanosleep grid barrier)
//   + software-pipelined staging (4-buffer ring, prefetch distance 2,
//     one syncwarp per stage)
//   + fused phase1(it=0) into the build
//   + dead final phase-3 / final barrier skipped.

#define NCTA 144
#define THREADS 1024
#define KL 8
#define BATCH 512
#define JOUT 10
#define ITERS 3
#define SB 384          // b's with u_hat in smem
#define SQ 6            // smem chunks of 64 b
#define RQ 2            // register chunks of 64 b
#define NCH 8           // total chunks
#define UHB 128         // floats per b row (swizzled, no pad)
#define WTB 68          // w_t row stride
#define XST 20          // xs row stride (16B-aligned, low-conflict)

#define SMEM_FLOATS (SB*UHB + 4*64*XST + 16*WTB + KL*JOUT + KL + 1024)
#define SMEM_BYTES (SMEM_FLOATS * 4)

typedef unsigned long long ull;

__device__ float g_spart[NCTA * BATCH * 16];
__device__ float g_v[BATCH * 16];
__device__ unsigned g_count;
__device__ volatile unsigned g_sense;

__device__ __forceinline__ ull f2_pk(float lo, float hi) {
    ull r; asm("mov.b64 %0,{%1,%2};" : "=l"(r) : "f"(lo), "f"(hi)); return r;
}
__device__ __forceinline__ float2 f2_up(ull a) {
    float2 r; asm("mov.b64 {%0,%1},%2;" : "=f"(r.x), "=f"(r.y) : "l"(a)); return r;
}
__device__ __forceinline__ ull f2_fma(ull a, ull b, ull c) {
    ull d; asm("fma.rn.f32x2 %0,%1,%2,%3;" : "=l"(d) : "l"(a), "l"(b), "l"(c)); return d;
}
__device__ __forceinline__ ull f2_mul(ull a, ull b) {
    ull d; asm("mul.rn.f32x2 %0,%1,%2;" : "=l"(d) : "l"(a), "l"(b)); return d;
}
__device__ __forceinline__ ull f2_add(ull a, ull b) {
    ull d; asm("add.rn.f32x2 %0,%1,%2;" : "=l"(d) : "l"(a), "l"(b)); return d;
}

// swizzled word offset of the h-th float4 (h=0: kl0-3, h=1: kl4-7) for vector idx u
__device__ __forceinline__ int uoff(int u, int h) { return (u * 8 + h * 4) ^ (u & 4); }

// R2 barrier (empirically best): one counter + one sense word, waiters poll
// with nanosleep backoff. Monotonic sense, count self-resets: replay-safe.
__device__ __forceinline__ void grid_barrier() {
    __syncthreads();
    if (threadIdx.x == 0) {
        __threadfence();                       // release
        const unsigned gen = g_sense;
        if (atomicAdd(&g_count, 1u) == NCTA - 1) {
            g_count = 0;
            __threadfence();
            g_sense = gen + 1;
        } else {
            while (g_sense == gen) __nanosleep(64);
        }
        __threadfence();                       // acquire
    }
    __syncthreads();
}

__global__ void __launch_bounds__(THREADS, 1)
caps_routing_kernel(const float* __restrict__ x,   // [512,1152,8]
                    const float* __restrict__ W,   // [10,1152,8,16]
                    float* __restrict__ out)       // [512,10,16]
{
    extern __shared__ float sm[];
    float* uh_s    = sm;                     // SB*UHB
    float* xs      = uh_s + SB * UHB;        // 4-buffer x staging ring
    float* w_t     = xs + 4 * 64 * XST;      // 16*WTB : w_t[u][kl*8+d]
    float* bs      = w_t + 16 * WTB;         // KL*JOUT b_IJ rows
    float* c_s     = bs + KL * JOUT;         // KL coupling coeffs
    float* scratch = c_s + KL;               // 1024 reduction scratch

    const int t    = threadIdx.x;
    const int cta  = blockIdx.x;
    const int k0   = cta * KL;
    const int u    = t & 15;
    const int bg   = t >> 4;                 // 0..63
    const int lane = t & 31;
    const int warp = t >> 5;

    ull uhr[RQ][4];                          // register u_hat for b in [384,512)

    for (int i = t; i < KL * JOUT; i += THREADS) bs[i] = 0.f;
    if (t < KL) c_s[t] = 0.1f;               // softmax(0) over 10
    __syncthreads();

    // per-thread x element address base: x[b=bg(+64*ch), k0.., qi*16+u]
    const float* xbase = x + ((size_t)bg * 1152 + k0) * 8 + u;
    // stage s (=qi*8+ch) load offset: ch*64 rows of 9216 + qi*16
    #define XADDR(s_) (xbase + (size_t)((s_) & 7) * 64 * 9216 + ((s_) >> 3) * 16)
    // this thread's staging slot in ring buffer p
    #define XSLOT(p_) (xs + (((p_) * 64) + bg) * XST + u)

    for (int j = 0; j < JOUT; ++j) {
        // ---- W[j, k0+kl, d, uu] -> w_t[uu][kl*8+d] ----
        {
            const int kl = t >> 7, rest = t & 127;
            const int d = rest >> 4, uu = rest & 15;
            w_t[uu * WTB + kl * 8 + d] = W[(size_t)(j * 1152 + k0 + kl) * 128 + rest];
        }
        __syncthreads();

        float s0acc[NCH];                     // fused phase1 (it=0) accumulators
        #pragma unroll
        for (int ch = 0; ch < NCH; ++ch) s0acc[ch] = 0.f;

        // ---- pipelined build: prefetch distance 2, ring of 4 buffers ----
        {
            float xv0 = *XADDR(0);
            float xv1 = *XADDR(1);
            *XSLOT(0) = xv0;
            *XSLOT(1) = xv1;

            ulonglong2 Wq0a, Wq0b, Wq1a, Wq1b;
            float clo = 0.f, chi = 0.f;

            #pragma unroll
            for (int s = 0; s < 32; ++s) {
                __syncwarp();                 // STS(s) visible to the 16-lane group
                float xvn;
                if (s + 2 < 32) xvn = *XADDR(s + 2);

                const int qi = s >> 3, ch = s & 7;
                if (ch == 0) {                // new kl-quarter: refresh W registers
                    const float* wr = w_t + u * WTB + qi * 16;
                    Wq0a = *reinterpret_cast<const ulonglong2*>(wr);
                    Wq0b = *reinterpret_cast<const ulonglong2*>(wr + 4);
                    Wq1a = *reinterpret_cast<const ulonglong2*>(wr + 8);
                    Wq1b = *reinterpret_cast<const ulonglong2*>(wr + 12);
                    clo = c_s[qi * 2]; chi = c_s[qi * 2 + 1];
                }

                const float* xrow = xs + ((s & 3) * 64 + bg) * XST;
                const ulonglong2 X0 = *reinterpret_cast<const ulonglong2*>(xrow);
                const ulonglong2 X1 = *reinterpret_cast<const ulonglong2*>(xrow + 4);
                const ulonglong2 X2 = *reinterpret_cast<const ulonglong2*>(xrow + 8);
                const ulonglong2 X3 = *reinterpret_cast<const ulonglong2*>(xrow + 12);

                float a0, a1;
                {
                    ull acc = f2_mul(X0.x, Wq0a.x);
                    acc = f2_fma(X0.y, Wq0a.y, acc);
                    acc = f2_fma(X1.x, Wq0b.x, acc);
                    acc = f2_fma(X1.y, Wq0b.y, acc);
                    const float2 p = f2_up(acc);
                    a0 = p.x + p.y;
                }
                {
                    ull acc = f2_mul(X2.x, Wq1a.x);
                    acc = f2_fma(X2.y, Wq1a.y, acc);
                    acc = f2_fma(X3.x, Wq1b.x, acc);
                    acc = f2_fma(X3.y, Wq1b.y, acc);
                    const float2 p = f2_up(acc);
                    a1 = p.x + p.y;
                }
                s0acc[ch] = fmaf(a1, chi, fmaf(a0, clo, s0acc[ch]));
                if (ch < SQ) {
                    const int off = (u * 8 + qi * 2) ^ (u & 4);
                    *reinterpret_cast<float2*>(uh_s + (ch * 64 + bg) * UHB + off)
                        = make_float2(a0, a1);
                } else {
                    uhr[ch - SQ][qi] = f2_pk(a0, a1);
                }

                if (s + 2 < 32) *XSLOT((s + 2) & 3) = xvn;
            }
        }

        // fused phase1 (it=0) store
        #pragma unroll
        for (int ch = 0; ch < NCH; ++ch)
            __stcg(&g_spart[((size_t)cta * BATCH + ch * 64 + bg) * 16 + u], s0acc[ch]);

        for (int it = 0; it < ITERS; ++it) {
            const bool last = (j == JOUT - 1) && (it == ITERS - 1);

            // ---------- phase 1 (it>=1): partial s over this CTA's 8 k's ----------
            if (it > 0) {
                const ull c01 = f2_pk(c_s[0], c_s[1]);
                const ull c23 = f2_pk(c_s[2], c_s[3]);
                const ull c45 = f2_pk(c_s[4], c_s[5]);
                const ull c67 = f2_pk(c_s[6], c_s[7]);
                #pragma unroll
                for (int q = 0; q < SQ; ++q) {
                    const int b = q * 64 + bg;
                    const float* src = uh_s + b * UHB;
                    const ulonglong2 A  = *reinterpret_cast<const ulonglong2*>(src + uoff(u, 0));
                    const ulonglong2 Bv = *reinterpret_cast<const ulonglong2*>(src + uoff(u, 1));
                    ull s0 = f2_mul(A.x, c01);
                    ull s1 = f2_mul(A.y, c23);
                    s0 = f2_fma(Bv.x, c45, s0);
                    s1 = f2_fma(Bv.y, c67, s1);
                    const float2 p = f2_up(f2_add(s0, s1));
                    __stcg(&g_spart[((size_t)cta * BATCH + b) * 16 + u], p.x + p.y);
                }
                #pragma unroll
                for (int q = 0; q < RQ; ++q) {
                    const int b = SB + q * 64 + bg;
                    ull s0 = f2_mul(uhr[q][0], c01);
                    ull s1 = f2_mul(uhr[q][1], c23);
                    s0 = f2_fma(uhr[q][2], c45, s0);
                    s1 = f2_fma(uhr[q][3], c67, s1);
                    const float2 p = f2_up(f2_add(s0, s1));
                    __stcg(&g_spart[((size_t)cta * BATCH + b) * 16 + u], p.x + p.y);
                }
            }
            grid_barrier();

            // ---------- phase 2: reduce 144 partials, squash -> v ----------
            if (cta < 128) {
                const int bl  = (t >> 4) & 3;
                const int ch2 = t >> 6;                     // 0..15
                const int b   = cta * 4 + bl;
                float p = 0.f;
                for (int i = ch2; i < NCTA; i += 16)
                    p += __ldcg(&g_spart[((size_t)i * BATCH + b) * 16 + u]);
                scratch[ch2 * 64 + bl * 16 + u] = p;
                __syncthreads();
                if (t < 64) {
                    float s = 0.f;
                    #pragma unroll
                    for (int c2 = 0; c2 < 16; ++c2) s += scratch[c2 * 64 + t];
                    float sq = s * s;
                    #pragma unroll
                    for (int m = 8; m >= 1; m >>= 1)
                        sq += __shfl_xor_sync(0xffffffffu, sq, m);
                    const float v = s * sq / ((1.f + sq) * (sqrtf(sq) + 1e-7f));
                    const int bb = cta * 4 + (t >> 4);
                    if (!last)
                        __stcg(&g_v[bb * 16 + (t & 15)], v);
                    if (it == ITERS - 1)
                        out[((size_t)bb * JOUT + j) * 16 + (t & 15)] = v;
                }
            }
            if (last) break;                   // final v written; no p3 needed
            grid_barrier();

            // ---------- phase 3: agree, b_IJ update, next c (CTA-local) ----------
            {
                ull ag0 = 0ull, ag1 = 0ull, ag2 = 0ull, ag3 = 0ull;
                #pragma unroll
                for (int q = 0; q < SQ; ++q) {
                    const int b = q * 64 + bg;
                    const float vv = __ldcg(&g_v[b * 16 + u]);
                    const ull vp = f2_pk(vv, vv);
                    const float* src = uh_s + b * UHB;
                    const ulonglong2 A  = *reinterpret_cast<const ulonglong2*>(src + uoff(u, 0));
                    const ulonglong2 Bv = *reinterpret_cast<const ulonglong2*>(src + uoff(u, 1));
                    ag0 = f2_fma(A.x,  vp, ag0);
                    ag1 = f2_fma(A.y,  vp, ag1);
                    ag2 = f2_fma(Bv.x, vp, ag2);
                    ag3 = f2_fma(Bv.y, vp, ag3);
                }
                #pragma unroll
                for (int q = 0; q < RQ; ++q) {
                    const int b = SB + q * 64 + bg;
                    const float vv = __ldcg(&g_v[b * 16 + u]);
                    const ull vp = f2_pk(vv, vv);
                    ag0 = f2_fma(uhr[q][0], vp, ag0);
                    ag1 = f2_fma(uhr[q][1], vp, ag1);
                    ag2 = f2_fma(uhr[q][2], vp, ag2);
                    ag3 = f2_fma(uhr[q][3], vp, ag3);
                }
                float ag[8];
                { float2 p;
                  p = f2_up(ag0); ag[0] = p.x; ag[1] = p.y;
                  p = f2_up(ag1); ag[2] = p.x; ag[3] = p.y;
                  p = f2_up(ag2); ag[4] = p.x; ag[5] = p.y;
                  p = f2_up(ag3); ag[6] = p.x; ag[7] = p.y; }
                #pragma unroll
                for (int kl = 0; kl < KL; ++kl) {
                    float v = ag[kl];
                    #pragma unroll
                    for (int m = 16; m >= 1; m >>= 1)
                        v += __shfl_xor_sync(0xffffffffu, v, m);
                    if (lane == 0) scratch[warp * KL + kl] = v;
                }
                __syncthreads();
                if (t < KL) {
                    float s = 0.f;
                    #pragma unroll
                    for (int w2 = 0; w2 < 32; ++w2) s += scratch[w2 * KL + t];
                    bs[t * JOUT + j] += s;
                    const int jn = (it < ITERS - 1) ? j : j + 1;
                    if (jn < JOUT) {
                        float m = bs[t * JOUT];
                        #pragma unroll
                        for (int jj = 1; jj < JOUT; ++jj)
                            m = fmaxf(m, bs[t * JOUT + jj]);
                        float den = 0.f, num = 0.f;
                        #pragma unroll
                        for (int jj = 0; jj < JOUT; ++jj) {
                            const float e = expf(bs[t * JOUT + jj] - m);
                            den += e;
                            if (jj == jn) num = e;
                        }
                        c_s[t] = num / den;
                    }
                }
                __syncthreads();
            }
        } // it
    } // j
}

extern "C" void kernel_launch(void* const* d_in, const int* in_sizes, int n_in,
                              void* d_out, int out_size) {
    const float* x = (const float*)d_in[0];   // [512,1152,8,1]
    const float* W = (const float*)d_in[1];   // [10,1152,8,16]
    float* out = (float*)d_out;               // [512,10,16,1]
    (void)in_sizes; (void)n_in; (void)out_size;

    cudaFuncSetAttribute(caps_routing_kernel,
                         cudaFuncAttributeMaxDynamicSharedMemorySize, SMEM_BYTES);
    caps_routing_kernel<<<NCTA, THREADS, SMEM_BYTES>>>(x, W, out);
}